// round 14
// baseline (speedup 1.0000x reference)
#include <cuda_runtime.h>

// NBVLoss: weighted BCE sum over predictions[16384,4096], target[16384,4096] (t in {0,1})
//   out = sum_i  w(t_i) * ( -max(log-term_i, -100) )
//   w(1) = 1.6 applied to -log(p);  w(0) = 0.4 applied to -log1p(-p)
//
// HBM-bound streaming reduction: grid-stride float4, per-thread fp32 acc,
// block reduce -> __device__ scratch, one-block finisher -> d_out[0].
// No atomics (deterministic), no d_out pre-zero needed.

#define NBV_BLOCKS  2048
#define NBV_THREADS 256

__device__ float g_nbv_partials[NBV_BLOCKS];

__device__ __forceinline__ float nbv_term(float p, float t) {
    // t is exactly 0.0f or 1.0f
    float l = (t != 0.0f) ? logf(p) : log1pf(-p);   // logf(0) = -inf, clamped below
    l = fmaxf(l, -100.0f);
    float w = (t != 0.0f) ? 1.6f : 0.4f;
    return -w * l;
}

__global__ void __launch_bounds__(NBV_THREADS)
nbv_partial_kernel(const float4* __restrict__ pred4,
                   const float4* __restrict__ targ4,
                   long long n4)
{
    float acc = 0.0f;
    const long long stride = (long long)gridDim.x * blockDim.x;
    for (long long i = (long long)blockIdx.x * blockDim.x + threadIdx.x;
         i < n4; i += stride) {
        float4 p = pred4[i];
        float4 t = targ4[i];
        acc += nbv_term(p.x, t.x);
        acc += nbv_term(p.y, t.y);
        acc += nbv_term(p.z, t.z);
        acc += nbv_term(p.w, t.w);
    }

    // warp reduce
    #pragma unroll
    for (int off = 16; off > 0; off >>= 1)
        acc += __shfl_xor_sync(0xFFFFFFFFu, acc, off);

    // block reduce via smem (one value per warp)
    __shared__ float s_warp[NBV_THREADS / 32];
    const int lane = threadIdx.x & 31;
    const int wid  = threadIdx.x >> 5;
    if (lane == 0) s_warp[wid] = acc;
    __syncthreads();

    if (wid == 0) {
        float v = (lane < NBV_THREADS / 32) ? s_warp[lane] : 0.0f;
        #pragma unroll
        for (int off = 16; off > 0; off >>= 1)
            v += __shfl_xor_sync(0xFFFFFFFFu, v, off);
        if (lane == 0) g_nbv_partials[blockIdx.x] = v;
    }
}

__global__ void __launch_bounds__(1024)
nbv_final_kernel(float* __restrict__ out)
{
    // single block of 1024 threads reduces NBV_BLOCKS partials
    float acc = 0.0f;
    for (int i = threadIdx.x; i < NBV_BLOCKS; i += 1024)
        acc += g_nbv_partials[i];

    #pragma unroll
    for (int off = 16; off > 0; off >>= 1)
        acc += __shfl_xor_sync(0xFFFFFFFFu, acc, off);

    __shared__ float s_warp[32];
    const int lane = threadIdx.x & 31;
    const int wid  = threadIdx.x >> 5;
    if (lane == 0) s_warp[wid] = acc;
    __syncthreads();

    if (wid == 0) {
        float v = (lane < 32) ? s_warp[lane] : 0.0f;
        #pragma unroll
        for (int off = 16; off > 0; off >>= 1)
            v += __shfl_xor_sync(0xFFFFFFFFu, v, off);
        if (lane == 0) out[0] = v;
    }
}

extern "C" void kernel_launch(void* const* d_in, const int* in_sizes, int n_in,
                              void* d_out, int out_size)
{
    const float* pred = (const float*)d_in[0];
    const float* targ = (const float*)d_in[1];
    float* out = (float*)d_out;

    const long long n  = (long long)in_sizes[0];  // 16384*4096, divisible by 4
    const long long n4 = n >> 2;

    nbv_partial_kernel<<<NBV_BLOCKS, NBV_THREADS>>>(
        (const float4*)pred, (const float4*)targ, n4);
    nbv_final_kernel<<<1, 1024>>>(out);
}

// round 15
// speedup vs baseline: 1.7269x; 1.7269x over previous
#include <cuda_runtime.h>

// NBVLoss: weighted BCE sum over predictions[16384,4096], target[16384,4096], t in {0,1}
//   out = sum_i  w_i * ( -max(log x_i, -100) ),  x_i = t? p : 1-p,  w = t? 1.6 : 0.4
//
// Single-pass streaming reduction:
//   - float4 grid-stride, 4x manual unroll (8 LDG.128 front-batched -> MLP)
//   - single __logf per element (t is exactly 0/1, so the two BCE terms collapse)
//   - block reduce -> __device__ scratch; LAST block (atomic ticket) reduces
//     partials and writes d_out[0]. Deterministic order, no second launch.

#define NBV_BLOCKS  2048
#define NBV_THREADS 256

__device__ float        g_nbv_partials[NBV_BLOCKS];
__device__ unsigned int g_nbv_ticket;   // zero-init; reset to 0 by last block each launch

__device__ __forceinline__ float nbv_term(float p, float t) {
    // t is exactly 0.0f or 1.0f
    float x = (t != 0.0f) ? p : (1.0f - p);
    float w = (t != 0.0f) ? -1.6f : -0.4f;
    float l = fmaxf(__logf(x), -100.0f);   // __logf(0) = -inf, clamped
    return w * l;
}

__device__ __forceinline__ float nbv_quad(float4 p, float4 t) {
    return nbv_term(p.x, t.x) + nbv_term(p.y, t.y)
         + nbv_term(p.z, t.z) + nbv_term(p.w, t.w);
}

__device__ __forceinline__ float block_reduce(float acc, float* s_warp, int nwarps) {
    #pragma unroll
    for (int off = 16; off > 0; off >>= 1)
        acc += __shfl_xor_sync(0xFFFFFFFFu, acc, off);
    const int lane = threadIdx.x & 31;
    const int wid  = threadIdx.x >> 5;
    if (lane == 0) s_warp[wid] = acc;
    __syncthreads();
    float v = 0.0f;
    if (wid == 0) {
        v = (lane < nwarps) ? s_warp[lane] : 0.0f;
        #pragma unroll
        for (int off = 16; off > 0; off >>= 1)
            v += __shfl_xor_sync(0xFFFFFFFFu, v, off);
    }
    return v;  // valid in warp 0
}

__global__ void __launch_bounds__(NBV_THREADS)
nbv_kernel(const float4* __restrict__ pred4,
           const float4* __restrict__ targ4,
           long long n4,
           float* __restrict__ out)
{
    const long long stride = (long long)gridDim.x * blockDim.x;
    long long i = (long long)blockIdx.x * blockDim.x + threadIdx.x;

    float acc = 0.0f;

    // main loop: 4 pairs in flight (8 x LDG.128 front-batched)
    for (; i + 3 * stride < n4; i += 4 * stride) {
        float4 p0 = pred4[i];
        float4 p1 = pred4[i + stride];
        float4 p2 = pred4[i + 2 * stride];
        float4 p3 = pred4[i + 3 * stride];
        float4 t0 = targ4[i];
        float4 t1 = targ4[i + stride];
        float4 t2 = targ4[i + 2 * stride];
        float4 t3 = targ4[i + 3 * stride];
        acc += nbv_quad(p0, t0);
        acc += nbv_quad(p1, t1);
        acc += nbv_quad(p2, t2);
        acc += nbv_quad(p3, t3);
    }
    // tail
    for (; i < n4; i += stride)
        acc += nbv_quad(pred4[i], targ4[i]);

    __shared__ float s_warp[NBV_THREADS / 32];
    float bsum = block_reduce(acc, s_warp, NBV_THREADS / 32);

    __shared__ bool s_last;
    if (threadIdx.x == 0) {
        g_nbv_partials[blockIdx.x] = bsum;
        __threadfence();
        unsigned int tk = atomicAdd(&g_nbv_ticket, 1u);
        s_last = (tk == (unsigned int)(gridDim.x - 1));
    }
    __syncthreads();

    if (s_last) {
        // this block sees all partials (threadfence + atomic acquire chain)
        float a = 0.0f;
        for (int j = threadIdx.x; j < (int)gridDim.x; j += NBV_THREADS)
            a += g_nbv_partials[j];
        __shared__ float s_warp2[NBV_THREADS / 32];
        float total = block_reduce(a, s_warp2, NBV_THREADS / 32);
        if (threadIdx.x == 0) {
            out[0] = total;
            g_nbv_ticket = 0;   // reset for next graph replay
        }
    }
}

extern "C" void kernel_launch(void* const* d_in, const int* in_sizes, int n_in,
                              void* d_out, int out_size)
{
    const float* pred = (const float*)d_in[0];
    const float* targ = (const float*)d_in[1];
    float* out = (float*)d_out;

    const long long n  = (long long)in_sizes[0];  // divisible by 4
    const long long n4 = n >> 2;

    nbv_kernel<<<NBV_BLOCKS, NBV_THREADS>>>(
        (const float4*)pred, (const float4*)targ, n4, out);
}

// round 16
// speedup vs baseline: 1.8091x; 1.0476x over previous
#include <cuda_runtime.h>

// NBVLoss: weighted BCE sum over predictions[16384,4096], target[16384,4096], t in {0,1}
//   out = sum_i  w_i * ( -max(log x_i, -100) ),  x_i = t? p : 1-p,  w = t? 1.6 : 0.4
//
// HBM-streaming reduction at the roofline:
//   - float4 grid-stride, 4x manual unroll (8 front-batched LDG.128 -> MLP)
//   - __ldcs streaming loads (zero reuse; don't pollute L2)
//   - 32-bit indexing (n < 2^31) to cut IMAD.WIDE address chains
//   - single __logf per element (t is exactly 0/1 -> BCE terms collapse)
//   - block reduce -> __device__ scratch; last block (atomic ticket) finishes
//     and writes d_out[0]. Deterministic, single launch.

#define NBV_BLOCKS  2048
#define NBV_THREADS 256

__device__ float        g_nbv_partials[NBV_BLOCKS];
__device__ unsigned int g_nbv_ticket;   // zero-init; reset by last block each launch

__device__ __forceinline__ float nbv_term(float p, float t) {
    // t is exactly 0.0f or 1.0f
    float x = (t != 0.0f) ? p : (1.0f - p);
    float w = (t != 0.0f) ? -1.6f : -0.4f;
    float l = fmaxf(__logf(x), -100.0f);   // __logf(0) = -inf, clamped
    return w * l;
}

__device__ __forceinline__ float nbv_quad(float4 p, float4 t) {
    return nbv_term(p.x, t.x) + nbv_term(p.y, t.y)
         + nbv_term(p.z, t.z) + nbv_term(p.w, t.w);
}

__device__ __forceinline__ float block_reduce(float acc, float* s_warp, int nwarps) {
    #pragma unroll
    for (int off = 16; off > 0; off >>= 1)
        acc += __shfl_xor_sync(0xFFFFFFFFu, acc, off);
    const int lane = threadIdx.x & 31;
    const int wid  = threadIdx.x >> 5;
    if (lane == 0) s_warp[wid] = acc;
    __syncthreads();
    float v = 0.0f;
    if (wid == 0) {
        v = (lane < nwarps) ? s_warp[lane] : 0.0f;
        #pragma unroll
        for (int off = 16; off > 0; off >>= 1)
            v += __shfl_xor_sync(0xFFFFFFFFu, v, off);
    }
    return v;  // valid in warp 0
}

__global__ void __launch_bounds__(NBV_THREADS, 8)
nbv_kernel(const float4* __restrict__ pred4,
           const float4* __restrict__ targ4,
           unsigned int n4,
           float* __restrict__ out)
{
    const unsigned int stride = gridDim.x * blockDim.x;
    unsigned int i = blockIdx.x * blockDim.x + threadIdx.x;

    float acc = 0.0f;

    // main loop: 4 pairs in flight (8 x LDG.128.LU front-batched)
    for (; i + 3u * stride < n4; i += 4u * stride) {
        float4 p0 = __ldcs(pred4 + i);
        float4 p1 = __ldcs(pred4 + i + stride);
        float4 p2 = __ldcs(pred4 + i + 2u * stride);
        float4 p3 = __ldcs(pred4 + i + 3u * stride);
        float4 t0 = __ldcs(targ4 + i);
        float4 t1 = __ldcs(targ4 + i + stride);
        float4 t2 = __ldcs(targ4 + i + 2u * stride);
        float4 t3 = __ldcs(targ4 + i + 3u * stride);
        acc += nbv_quad(p0, t0);
        acc += nbv_quad(p1, t1);
        acc += nbv_quad(p2, t2);
        acc += nbv_quad(p3, t3);
    }
    // tail
    for (; i < n4; i += stride)
        acc += nbv_quad(__ldcs(pred4 + i), __ldcs(targ4 + i));

    __shared__ float s_warp[NBV_THREADS / 32];
    float bsum = block_reduce(acc, s_warp, NBV_THREADS / 32);

    __shared__ bool s_last;
    if (threadIdx.x == 0) {
        g_nbv_partials[blockIdx.x] = bsum;
        __threadfence();
        unsigned int tk = atomicAdd(&g_nbv_ticket, 1u);
        s_last = (tk == gridDim.x - 1u);
    }
    __syncthreads();

    if (s_last) {
        float a = 0.0f;
        for (int j = threadIdx.x; j < (int)gridDim.x; j += NBV_THREADS)
            a += g_nbv_partials[j];
        __shared__ float s_warp2[NBV_THREADS / 32];
        float total = block_reduce(a, s_warp2, NBV_THREADS / 32);
        if (threadIdx.x == 0) {
            out[0] = total;
            g_nbv_ticket = 0;   // reset for next graph replay
        }
    }
}

extern "C" void kernel_launch(void* const* d_in, const int* in_sizes, int n_in,
                              void* d_out, int out_size)
{
    const float* pred = (const float*)d_in[0];
    const float* targ = (const float*)d_in[1];
    float* out = (float*)d_out;

    const unsigned int n  = (unsigned int)in_sizes[0];  // 16384*4096, divisible by 4
    const unsigned int n4 = n >> 2;

    nbv_kernel<<<NBV_BLOCKS, NBV_THREADS>>>(
        (const float4*)pred, (const float4*)targ, n4, out);
}